// round 3
// baseline (speedup 1.0000x reference)
#include <cuda_runtime.h>
#include <math.h>

#define VOX   4096
#define TPTS  100
#define KNN   8
#define NEG_INF (-3.402823466e38f)

// branchless sorted-insert of (d, jj) into desc-sorted v/id[8], strict > (stable ties)
__device__ __forceinline__ void ins8(float v[KNN], int id[KNN], float d, int jj) {
#pragma unroll
    for (int s = 0; s < KNN; s++) {
        bool gt = d > v[s];
        float vs = v[s]; int is = id[s];
        v[s]  = gt ? d  : vs;
        id[s] = gt ? jj : is;
        d     = gt ? vs : d;
        jj    = gt ? is : jj;
    }
}

__global__ __launch_bounds__(128, 6) void gcn_kernel(
    const float* __restrict__ features,   // [4096,100,4]
    const float* __restrict__ conv_w,     // [64,18]
    const float* __restrict__ bn_gamma,
    const float* __restrict__ bn_beta,
    const float* __restrict__ bn_mean,
    const float* __restrict__ bn_var,
    const int*   __restrict__ num_voxels, // [4096]
    const int*   __restrict__ coors,      // [4096,4]
    float*       __restrict__ out)        // [4096,64]
{
    __shared__ __align__(16) float s_feat[TPTS][12];  // 9 feat, [9]=xx
    __shared__ __align__(16) float s_a[TPTS * 64];    // a'; overlaid w/ topk candidates
    __shared__ __align__(16) float s_wa[9 * 64];
    __shared__ __align__(16) float s_wb[9 * 64];
    __shared__ __align__(16) float s_bias[64];
    __shared__ unsigned char s_idx[TPTS][KNN];
    __shared__ float s_red[16];
    __shared__ float s_mean[3];

    const int tid = threadIdx.x;
    const int vox = blockIdx.x;
    int nv = num_voxels[vox];
    if (nv < 1) nv = 1;
    if (nv > TPTS) nv = TPTS;

    // ---- fold BN into weights, per block (overlaps the feature load) ----
    if (tid < 64) {
        const int o = tid;
        float scale = bn_gamma[o] * rsqrtf(bn_var[o] + 1e-3f);
#pragma unroll
        for (int c = 0; c < 9; c++) {
            float w1 = conv_w[o * 18 + c];
            float w2 = conv_w[o * 18 + 9 + c];
            s_wa[c * 64 + o] = w1 * scale;
            s_wb[c * 64 + o] = (w2 - w1) * scale;
        }
        s_bias[o] = bn_beta[o] - bn_mean[o] * scale;
    }

    // ---- phase 1: load + mean over first 3 channels (warp shuffles) ----
    float4 fv = make_float4(0.f, 0.f, 0.f, 0.f);
    if (tid < TPTS)
        fv = reinterpret_cast<const float4*>(features)[vox * TPTS + tid];
    float sx = (tid < TPTS) ? fv.x : 0.f;
    float sy = (tid < TPTS) ? fv.y : 0.f;
    float sz = (tid < TPTS) ? fv.z : 0.f;
#pragma unroll
    for (int o = 16; o > 0; o >>= 1) {
        sx += __shfl_down_sync(0xffffffffu, sx, o);
        sy += __shfl_down_sync(0xffffffffu, sy, o);
        sz += __shfl_down_sync(0xffffffffu, sz, o);
    }
    if ((tid & 31) == 0) {
        int w = tid >> 5;
        s_red[w] = sx; s_red[4 + w] = sy; s_red[8 + w] = sz;
    }
    __syncthreads();
    if (tid == 0) {
        float fnv = (float)nv;
        s_mean[0] = (s_red[0] + s_red[1] + s_red[2] + s_red[3]) / fnv;
        s_mean[1] = (s_red[4] + s_red[5] + s_red[6] + s_red[7]) / fnv;
        s_mean[2] = (s_red[8] + s_red[9] + s_red[10] + s_red[11]) / fnv;
    }
    __syncthreads();

    const float cx = (float)coors[vox * 4 + 3] * 0.2f + 0.1f;
    const float cy = (float)coors[vox * 4 + 2] * 0.2f + (-39.9f);
    if (tid < TPTS) {
        float m = (tid < nv) ? 1.0f : 0.0f;
        float f[9];
        f[0] = fv.x * m;  f[1] = fv.y * m;  f[2] = fv.z * m;  f[3] = fv.w * m;
        f[4] = (fv.x - s_mean[0]) * m;
        f[5] = (fv.y - s_mean[1]) * m;
        f[6] = (fv.z - s_mean[2]) * m;
        f[7] = (fv.x - cx) * m;
        f[8] = (fv.y - cy) * m;
        float xx = 0.f;
#pragma unroll
        for (int c = 0; c < 9; c++) xx = fmaf(f[c], f[c], xx);
#pragma unroll
        for (int c = 0; c < 9; c++) s_feat[tid][c] = f[c];
        s_feat[tid][9]  = xx;
        s_feat[tid][10] = 0.f;
        s_feat[tid][11] = 0.f;
    }
    __syncthreads();

    // ---- phase 3: top-8 by key = 2*<xt,xj> - xx_j; half-major item layout so a
    //      warp's lanes scan the SAME j (broadcast LDS) ----
    float* candv = s_a;                          // [200][8] values
    int*   candi = (int*)(s_a + 2 * TPTS * KNN); // [200][8] ids
    const int h = nv >> 1;
    const int items = 2 * nv;
    for (int item = tid; item < items; item += 128) {
        const int half = (item >= nv) ? 1 : 0;
        const int t    = half ? (item - nv) : item;
        const int j0   = half ? h  : 0;
        const int j1   = half ? nv : h;
        const float4* fr = reinterpret_cast<const float4*>(s_feat[t]);
        float4 fa = fr[0], fb = fr[1];
        float  f8 = s_feat[t][8];

        float v[KNN]; int id[KNN];
#pragma unroll
        for (int k = 0; k < KNN; k++) { v[k] = NEG_INF; id[k] = 0; }

#pragma unroll 2
        for (int j = j0; j < j1; j++) {
            const float* row = s_feat[j];
            float4 ja = reinterpret_cast<const float4*>(row)[0];
            float4 jb = reinterpret_cast<const float4*>(row)[1];
            float2 jc = *reinterpret_cast<const float2*>(row + 8);
            float inner = 0.f;
            inner = fmaf(fa.x, ja.x, inner);
            inner = fmaf(fa.y, ja.y, inner);
            inner = fmaf(fa.z, ja.z, inner);
            inner = fmaf(fa.w, ja.w, inner);
            inner = fmaf(fb.x, jb.x, inner);
            inner = fmaf(fb.y, jb.y, inner);
            inner = fmaf(fb.z, jb.z, inner);
            inner = fmaf(fb.w, jb.w, inner);
            inner = fmaf(f8,   jc.x, inner);
            float key = fmaf(2.0f, inner, -jc.y);
            ins8(v, id, key, j);
        }
#pragma unroll
        for (int k = 0; k < KNN; k++) {
            candv[item * KNN + k] = v[k];
            candi[item * KNN + k] = id[k];
        }
    }
    __syncthreads();

    // merge the two halves per point (half0 first: lower j kept on ties), then
    // fill masked neighbors (key==0, ascending index)
    if (tid < nv) {
        const int t = tid;
        float v[KNN]; int id[KNN];
#pragma unroll
        for (int k = 0; k < KNN; k++) {
            v[k]  = candv[t * KNN + k];
            id[k] = candi[t * KNN + k];
        }
#pragma unroll
        for (int k = 0; k < KNN; k++) {
            float d = candv[(nv + t) * KNN + k];
            int  jj = candi[(nv + t) * KNN + k];
            ins8(v, id, d, jj);
        }
        for (int jm = nv; jm < TPTS; jm++) {
            if (!(0.f > v[KNN - 1])) break;
            ins8(v, id, 0.f, jm);
        }
#pragma unroll
        for (int k = 0; k < KNN; k++) s_idx[t][k] = (unsigned char)id[k];
    }
    __syncthreads();

    // ---- phase 2: a'[t][o] = (feat[t] . wa[:,o]) — overwrites candidate overlay ----
    for (int p = tid; p < TPTS * 16; p += 128) {
        int t  = p >> 4;
        int o4 = p & 15;
        const float4* fr = reinterpret_cast<const float4*>(s_feat[t]);
        float4 fa = fr[0], fb = fr[1];
        float  f8 = s_feat[t][8];
        float fs[9] = {fa.x, fa.y, fa.z, fa.w, fb.x, fb.y, fb.z, fb.w, f8};
        float4 acc = make_float4(0.f, 0.f, 0.f, 0.f);
#pragma unroll
        for (int c = 0; c < 9; c++) {
            float4 wv = *reinterpret_cast<const float4*>(&s_wa[c * 64 + o4 * 4]);
            acc.x = fmaf(fs[c], wv.x, acc.x);
            acc.y = fmaf(fs[c], wv.y, acc.y);
            acc.z = fmaf(fs[c], wv.z, acc.z);
            acc.w = fmaf(fs[c], wv.w, acc.w);
        }
        reinterpret_cast<float4*>(s_a)[t * 16 + o4] = acc;
    }
    __syncthreads();

    // ---- phase 4: lrelu(max_k a'[idx]+b'[t]) then max over t with 0 floor.
    //      slice in low 3 bits so the slice-reduction is intra-warp. ----
    {
        const int o4    = tid >> 3;   // 0..15
        const int slice = tid & 7;    // 0..7
        float4 rmax = make_float4(0.f, 0.f, 0.f, 0.f);
        for (int t = slice; t < nv; t += 8) {
            float4 m4 = make_float4(NEG_INF, NEG_INF, NEG_INF, NEG_INF);
#pragma unroll
            for (int k = 0; k < KNN; k++) {
                int j = (int)s_idx[t][k];
                float4 a = reinterpret_cast<const float4*>(s_a)[j * 16 + o4];
                m4.x = fmaxf(m4.x, a.x);
                m4.y = fmaxf(m4.y, a.y);
                m4.z = fmaxf(m4.z, a.z);
                m4.w = fmaxf(m4.w, a.w);
            }
            const float4* fr = reinterpret_cast<const float4*>(s_feat[t]);
            float4 fa = fr[0], fb = fr[1];
            float  f8 = s_feat[t][8];
            float fs[9] = {fa.x, fa.y, fa.z, fa.w, fb.x, fb.y, fb.z, fb.w, f8};
            float4 b = *reinterpret_cast<const float4*>(&s_bias[o4 * 4]);
#pragma unroll
            for (int c = 0; c < 9; c++) {
                float4 wv = *reinterpret_cast<const float4*>(&s_wb[c * 64 + o4 * 4]);
                b.x = fmaf(fs[c], wv.x, b.x);
                b.y = fmaf(fs[c], wv.y, b.y);
                b.z = fmaf(fs[c], wv.z, b.z);
                b.w = fmaf(fs[c], wv.w, b.w);
            }
            float4 hh;
            hh.x = m4.x + b.x;  hh.y = m4.y + b.y;
            hh.z = m4.z + b.z;  hh.w = m4.w + b.w;
            hh.x = (hh.x >= 0.f) ? hh.x : 0.2f * hh.x;
            hh.y = (hh.y >= 0.f) ? hh.y : 0.2f * hh.y;
            hh.z = (hh.z >= 0.f) ? hh.z : 0.2f * hh.z;
            hh.w = (hh.w >= 0.f) ? hh.w : 0.2f * hh.w;
            rmax.x = fmaxf(rmax.x, hh.x);
            rmax.y = fmaxf(rmax.y, hh.y);
            rmax.z = fmaxf(rmax.z, hh.z);
            rmax.w = fmaxf(rmax.w, hh.w);
        }
        // reduce over slice (low 3 lane bits) within the warp
#pragma unroll
        for (int off = 4; off > 0; off >>= 1) {
            rmax.x = fmaxf(rmax.x, __shfl_xor_sync(0xffffffffu, rmax.x, off));
            rmax.y = fmaxf(rmax.y, __shfl_xor_sync(0xffffffffu, rmax.y, off));
            rmax.z = fmaxf(rmax.z, __shfl_xor_sync(0xffffffffu, rmax.z, off));
            rmax.w = fmaxf(rmax.w, __shfl_xor_sync(0xffffffffu, rmax.w, off));
        }
        if (slice == 0)
            *reinterpret_cast<float4*>(&out[vox * 64 + o4 * 4]) = rmax;
    }
}

extern "C" void kernel_launch(void* const* d_in, const int* in_sizes, int n_in,
                              void* d_out, int out_size) {
    const float* features   = (const float*)d_in[0];
    const float* conv_w     = (const float*)d_in[1];
    const float* bn_gamma   = (const float*)d_in[2];
    const float* bn_beta    = (const float*)d_in[3];
    const float* bn_mean    = (const float*)d_in[4];
    const float* bn_var     = (const float*)d_in[5];
    const int*   num_voxels = (const int*)d_in[6];
    const int*   coors      = (const int*)d_in[7];
    float*       out        = (float*)d_out;

    gcn_kernel<<<VOX, 128>>>(features, conv_w, bn_gamma, bn_beta, bn_mean, bn_var,
                             num_voxels, coors, out);
}

// round 4
// speedup vs baseline: 1.7307x; 1.7307x over previous
#include <cuda_runtime.h>
#include <math.h>

#define VOX   4096
#define TPTS  100
#define KNN   8
#define NEG_INF (-3.402823466e38f)

// branchless sorted-insert, desc order, strict > (stable ties = lower j kept).
// Value path uses FMNMX (lat 4) so the carried d-chain avoids pred-as-guard (13 cyc).
__device__ __forceinline__ void ins8(float v[KNN], int id[KNN], float d, int jj) {
#pragma unroll
    for (int s = 0; s < KNN; s++) {
        float vs = v[s];
        int   is = id[s];
        bool  gt = d > vs;
        v[s] = fmaxf(vs, d);
        float dm = fminf(vs, d);
        id[s] = gt ? jj : is;
        jj    = gt ? is : jj;
        d = dm;
    }
}

__global__ __launch_bounds__(128, 6) void gcn_kernel(
    const float* __restrict__ features,   // [4096,100,4]
    const float* __restrict__ conv_w,     // [64,18]
    const float* __restrict__ bn_gamma,
    const float* __restrict__ bn_beta,
    const float* __restrict__ bn_mean,
    const float* __restrict__ bn_var,
    const int*   __restrict__ num_voxels, // [4096]
    const int*   __restrict__ coors,      // [4096,4]
    float*       __restrict__ out)        // [4096,64]
{
    __shared__ __align__(16) float s_feat[TPTS][12];  // 9 feat, [9]=xx
    __shared__ __align__(16) float s_a[TPTS * 64];    // a'; overlaid w/ topk candidates
    __shared__ __align__(16) float s_wa[9 * 64];
    __shared__ __align__(16) float s_wb[9 * 64];
    __shared__ __align__(16) float s_bias[64];
    __shared__ unsigned char s_idx[TPTS][KNN];
    __shared__ __align__(16) float s_scr[512];
    __shared__ float s_red[16];
    __shared__ float s_mean[3];

    const int tid = threadIdx.x;
    const int vox = blockIdx.x;
    int nv = num_voxels[vox];
    if (nv < 1) nv = 1;
    if (nv > TPTS) nv = TPTS;

    // ---- fold BN into weights (overlaps feature load) ----
    if (tid < 64) {
        const int o = tid;
        float scale = bn_gamma[o] * rsqrtf(bn_var[o] + 1e-3f);
#pragma unroll
        for (int c = 0; c < 9; c++) {
            float w1 = conv_w[o * 18 + c];
            float w2 = conv_w[o * 18 + 9 + c];
            s_wa[c * 64 + o] = w1 * scale;
            s_wb[c * 64 + o] = (w2 - w1) * scale;
        }
        s_bias[o] = bn_beta[o] - bn_mean[o] * scale;
    }

    // ---- phase 1: load + mean over first 3 channels ----
    float4 fv = make_float4(0.f, 0.f, 0.f, 0.f);
    if (tid < TPTS)
        fv = reinterpret_cast<const float4*>(features)[vox * TPTS + tid];
    float sx = (tid < TPTS) ? fv.x : 0.f;
    float sy = (tid < TPTS) ? fv.y : 0.f;
    float sz = (tid < TPTS) ? fv.z : 0.f;
#pragma unroll
    for (int o = 16; o > 0; o >>= 1) {
        sx += __shfl_down_sync(0xffffffffu, sx, o);
        sy += __shfl_down_sync(0xffffffffu, sy, o);
        sz += __shfl_down_sync(0xffffffffu, sz, o);
    }
    if ((tid & 31) == 0) {
        int w = tid >> 5;
        s_red[w] = sx; s_red[4 + w] = sy; s_red[8 + w] = sz;
    }
    __syncthreads();
    if (tid == 0) {
        float fnv = (float)nv;
        s_mean[0] = (s_red[0] + s_red[1] + s_red[2] + s_red[3]) / fnv;
        s_mean[1] = (s_red[4] + s_red[5] + s_red[6] + s_red[7]) / fnv;
        s_mean[2] = (s_red[8] + s_red[9] + s_red[10] + s_red[11]) / fnv;
    }
    __syncthreads();

    const float cx = (float)coors[vox * 4 + 3] * 0.2f + 0.1f;
    const float cy = (float)coors[vox * 4 + 2] * 0.2f + (-39.9f);
    if (tid < TPTS) {
        float m = (tid < nv) ? 1.0f : 0.0f;
        float f[9];
        f[0] = fv.x * m;  f[1] = fv.y * m;  f[2] = fv.z * m;  f[3] = fv.w * m;
        f[4] = (fv.x - s_mean[0]) * m;
        f[5] = (fv.y - s_mean[1]) * m;
        f[6] = (fv.z - s_mean[2]) * m;
        f[7] = (fv.x - cx) * m;
        f[8] = (fv.y - cy) * m;
        float xx = 0.f;
#pragma unroll
        for (int c = 0; c < 9; c++) xx = fmaf(f[c], f[c], xx);
#pragma unroll
        for (int c = 0; c < 9; c++) s_feat[tid][c] = f[c];
        s_feat[tid][9]  = xx;
        s_feat[tid][10] = 0.f;
        s_feat[tid][11] = 0.f;
    }
    __syncthreads();

    // ---- phase 3: top-8 by key = 2*<xt,xj> - xx_j ----
    float* candv = s_a;                          // [200][8] values
    int*   candi = (int*)(s_a + 2 * TPTS * KNN); // [200][8] ids
    const int h = nv >> 1;
    const int items = 2 * nv;
    for (int item = tid; item < items; item += 128) {
        int t    = item >> 1;
        int half = item & 1;
        int j0 = half ? h  : 0;
        int j1 = half ? nv : h;
        const float4* fr = reinterpret_cast<const float4*>(s_feat[t]);
        float4 fa = fr[0], fb = fr[1];
        float  f8 = s_feat[t][8];

        float v[KNN]; int id[KNN];
#pragma unroll
        for (int k = 0; k < KNN; k++) { v[k] = NEG_INF; id[k] = 0; }

#pragma unroll 2
        for (int j = j0; j < j1; j++) {
            const float* row = s_feat[j];
            float4 ja = reinterpret_cast<const float4*>(row)[0];
            float4 jb = reinterpret_cast<const float4*>(row)[1];
            float2 jc = *reinterpret_cast<const float2*>(row + 8);
            // two parallel FMA chains to halve the dot latency
            float i0 = 0.f, i1 = -0.5f * jc.y;   // fold -xx_j/2 into chain 1
            i0 = fmaf(fa.x, ja.x, i0);  i1 = fmaf(fa.y, ja.y, i1);
            i0 = fmaf(fa.z, ja.z, i0);  i1 = fmaf(fa.w, ja.w, i1);
            i0 = fmaf(fb.x, jb.x, i0);  i1 = fmaf(fb.y, jb.y, i1);
            i0 = fmaf(fb.z, jb.z, i0);  i1 = fmaf(fb.w, jb.w, i1);
            i0 = fmaf(f8,   jc.x, i0);
            float key = 2.0f * (i0 + i1);        // = 2*inner - xx_j
            ins8(v, id, key, j);
        }
#pragma unroll
        for (int k = 0; k < KNN; k++) {
            candv[item * KNN + k] = v[k];
            candi[item * KNN + k] = id[k];
        }
    }
    __syncthreads();

    // merge halves per point (half0 first: lower j kept on ties), fill masked (key==0)
    if (tid < nv) {
        const int t = tid;
        float v[KNN]; int id[KNN];
#pragma unroll
        for (int k = 0; k < KNN; k++) {
            v[k]  = candv[(2 * t) * KNN + k];
            id[k] = candi[(2 * t) * KNN + k];
        }
#pragma unroll
        for (int k = 0; k < KNN; k++) {
            float d = candv[(2 * t + 1) * KNN + k];
            int  jj = candi[(2 * t + 1) * KNN + k];
            ins8(v, id, d, jj);
        }
        for (int jm = nv; jm < TPTS; jm++) {
            if (!(0.f > v[KNN - 1])) break;
            ins8(v, id, 0.f, jm);
        }
#pragma unroll
        for (int k = 0; k < KNN; k++) s_idx[t][k] = (unsigned char)id[k];
    }
    __syncthreads();

    // ---- phase 2: a'[t][o] = feat[t] . wa[:,o] (overwrites candidate overlay) ----
    for (int p = tid; p < TPTS * 16; p += 128) {
        int t  = p >> 4;
        int o4 = p & 15;
        const float4* fr = reinterpret_cast<const float4*>(s_feat[t]);
        float4 fa = fr[0], fb = fr[1];
        float  f8 = s_feat[t][8];
        float fs[9] = {fa.x, fa.y, fa.z, fa.w, fb.x, fb.y, fb.z, fb.w, f8};
        float4 acc = make_float4(0.f, 0.f, 0.f, 0.f);
#pragma unroll
        for (int c = 0; c < 9; c++) {
            float4 wv = *reinterpret_cast<const float4*>(&s_wa[c * 64 + o4 * 4]);
            acc.x = fmaf(fs[c], wv.x, acc.x);
            acc.y = fmaf(fs[c], wv.y, acc.y);
            acc.z = fmaf(fs[c], wv.z, acc.z);
            acc.w = fmaf(fs[c], wv.w, acc.w);
        }
        reinterpret_cast<float4*>(s_a)[t * 16 + o4] = acc;
    }
    __syncthreads();

    // ---- phase 4 (R2 layout: o4 = low bits => contiguous gathers) ----
    {
        const int o4    = tid & 15;
        const int slice = tid >> 4;   // 0..7
        float4 rmax = make_float4(0.f, 0.f, 0.f, 0.f);
        for (int t = slice; t < nv; t += 8) {
            float4 m4 = make_float4(NEG_INF, NEG_INF, NEG_INF, NEG_INF);
#pragma unroll
            for (int k = 0; k < KNN; k++) {
                int j = (int)s_idx[t][k];
                float4 a = reinterpret_cast<const float4*>(s_a)[j * 16 + o4];
                m4.x = fmaxf(m4.x, a.x);
                m4.y = fmaxf(m4.y, a.y);
                m4.z = fmaxf(m4.z, a.z);
                m4.w = fmaxf(m4.w, a.w);
            }
            const float4* fr = reinterpret_cast<const float4*>(s_feat[t]);
            float4 fa = fr[0], fb = fr[1];
            float  f8 = s_feat[t][8];
            float fs[9] = {fa.x, fa.y, fa.z, fa.w, fb.x, fb.y, fb.z, fb.w, f8};
            float4 b = *reinterpret_cast<const float4*>(&s_bias[o4 * 4]);
#pragma unroll
            for (int c = 0; c < 9; c++) {
                float4 wv = *reinterpret_cast<const float4*>(&s_wb[c * 64 + o4 * 4]);
                b.x = fmaf(fs[c], wv.x, b.x);
                b.y = fmaf(fs[c], wv.y, b.y);
                b.z = fmaf(fs[c], wv.z, b.z);
                b.w = fmaf(fs[c], wv.w, b.w);
            }
            float4 hh;
            hh.x = m4.x + b.x;  hh.y = m4.y + b.y;
            hh.z = m4.z + b.z;  hh.w = m4.w + b.w;
            hh.x = (hh.x >= 0.f) ? hh.x : 0.2f * hh.x;
            hh.y = (hh.y >= 0.f) ? hh.y : 0.2f * hh.y;
            hh.z = (hh.z >= 0.f) ? hh.z : 0.2f * hh.z;
            hh.w = (hh.w >= 0.f) ? hh.w : 0.2f * hh.w;
            rmax.x = fmaxf(rmax.x, hh.x);
            rmax.y = fmaxf(rmax.y, hh.y);
            rmax.z = fmaxf(rmax.z, hh.z);
            rmax.w = fmaxf(rmax.w, hh.w);
        }
        reinterpret_cast<float4*>(s_scr)[slice * 16 + o4] = rmax;
    }
    __syncthreads();

    if (tid < 64) {
        float r = s_scr[tid];
#pragma unroll
        for (int s = 1; s < 8; s++) r = fmaxf(r, s_scr[s * 64 + tid]);
        out[vox * 64 + tid] = r;
    }
}

extern "C" void kernel_launch(void* const* d_in, const int* in_sizes, int n_in,
                              void* d_out, int out_size) {
    const float* features   = (const float*)d_in[0];
    const float* conv_w     = (const float*)d_in[1];
    const float* bn_gamma   = (const float*)d_in[2];
    const float* bn_beta    = (const float*)d_in[3];
    const float* bn_mean    = (const float*)d_in[4];
    const float* bn_var     = (const float*)d_in[5];
    const int*   num_voxels = (const int*)d_in[6];
    const int*   coors      = (const int*)d_in[7];
    float*       out        = (float*)d_out;

    gcn_kernel<<<VOX, 128>>>(features, conv_w, bn_gamma, bn_beta, bn_mean, bn_var,
                             num_voxels, coors, out);
}

// round 5
// speedup vs baseline: 2.1335x; 1.2328x over previous
#include <cuda_runtime.h>
#include <math.h>

#define VOX   4096
#define TPTS  100
#define KNN   8

// order-preserving float -> u32 (monotone increasing)
__device__ __forceinline__ unsigned ordf(float f) {
    unsigned u = __float_as_uint(f);
    unsigned m = (unsigned)((int)u >> 31);          // all-ones if negative
    return u ^ (m | 0x80000000u);
}
// pack: top 25 key bits (rounded) | (127 - j)  => desc sort = larger key, then lower j
__device__ __forceinline__ unsigned packkey(float key, int j) {
    unsigned u = ordf(key);
    return ((u + 0x40u) & 0xFFFFFF80u) | (unsigned)(127 - j);
}

// branchless top-8 insert on packed u32: 2 IMNMX per stage
__device__ __forceinline__ void ins8p(unsigned v[KNN], unsigned d) {
#pragma unroll
    for (int s = 0; s < KNN; s++) {
        unsigned vs = v[s];
        v[s] = vs > d ? vs : d;   // umax
        d    = vs > d ? d : vs;   // umin
    }
}

__global__ __launch_bounds__(128, 6) void gcn_kernel(
    const float* __restrict__ features,   // [4096,100,4]
    const float* __restrict__ conv_w,     // [64,18]
    const float* __restrict__ bn_gamma,
    const float* __restrict__ bn_beta,
    const float* __restrict__ bn_mean,
    const float* __restrict__ bn_var,
    const int*   __restrict__ num_voxels, // [4096]
    const int*   __restrict__ coors,      // [4096,4]
    float*       __restrict__ out)        // [4096,64]
{
    __shared__ __align__(16) float s_feat[TPTS][12];  // 9 feat, [9]=xx
    __shared__ __align__(16) float s_a[TPTS * 64];    // a'; overlaid w/ topk candidates
    __shared__ __align__(16) float s_wa[9 * 64];      // dead after phase 2 -> scr overlay
    __shared__ __align__(16) float s_wb[9 * 64];
    __shared__ __align__(16) float s_bias[64];
    __shared__ unsigned char s_idx[TPTS][KNN];
    __shared__ float s_red[16];
    __shared__ float s_mean[3];

    const int tid = threadIdx.x;
    const int vox = blockIdx.x;
    int nv = num_voxels[vox];
    if (nv < 1) nv = 1;
    if (nv > TPTS) nv = TPTS;

    // ---- fold BN into weights (overlaps feature load) ----
    if (tid < 64) {
        const int o = tid;
        float scale = bn_gamma[o] * rsqrtf(bn_var[o] + 1e-3f);
#pragma unroll
        for (int c = 0; c < 9; c++) {
            float w1 = conv_w[o * 18 + c];
            float w2 = conv_w[o * 18 + 9 + c];
            s_wa[c * 64 + o] = w1 * scale;
            s_wb[c * 64 + o] = (w2 - w1) * scale;
        }
        s_bias[o] = bn_beta[o] - bn_mean[o] * scale;
    }

    // ---- phase 1: load + mean over first 3 channels ----
    float4 fv = make_float4(0.f, 0.f, 0.f, 0.f);
    if (tid < TPTS)
        fv = reinterpret_cast<const float4*>(features)[vox * TPTS + tid];
    float sx = (tid < TPTS) ? fv.x : 0.f;
    float sy = (tid < TPTS) ? fv.y : 0.f;
    float sz = (tid < TPTS) ? fv.z : 0.f;
#pragma unroll
    for (int o = 16; o > 0; o >>= 1) {
        sx += __shfl_down_sync(0xffffffffu, sx, o);
        sy += __shfl_down_sync(0xffffffffu, sy, o);
        sz += __shfl_down_sync(0xffffffffu, sz, o);
    }
    if ((tid & 31) == 0) {
        int w = tid >> 5;
        s_red[w] = sx; s_red[4 + w] = sy; s_red[8 + w] = sz;
    }
    __syncthreads();
    if (tid == 0) {
        float fnv = (float)nv;
        s_mean[0] = (s_red[0] + s_red[1] + s_red[2] + s_red[3]) / fnv;
        s_mean[1] = (s_red[4] + s_red[5] + s_red[6] + s_red[7]) / fnv;
        s_mean[2] = (s_red[8] + s_red[9] + s_red[10] + s_red[11]) / fnv;
    }
    __syncthreads();

    const float cx = (float)coors[vox * 4 + 3] * 0.2f + 0.1f;
    const float cy = (float)coors[vox * 4 + 2] * 0.2f + (-39.9f);
    if (tid < TPTS) {
        float m = (tid < nv) ? 1.0f : 0.0f;
        float f[9];
        f[0] = fv.x * m;  f[1] = fv.y * m;  f[2] = fv.z * m;  f[3] = fv.w * m;
        f[4] = (fv.x - s_mean[0]) * m;
        f[5] = (fv.y - s_mean[1]) * m;
        f[6] = (fv.z - s_mean[2]) * m;
        f[7] = (fv.x - cx) * m;
        f[8] = (fv.y - cy) * m;
        float xx = 0.f;
#pragma unroll
        for (int c = 0; c < 9; c++) xx = fmaf(f[c], f[c], xx);
#pragma unroll
        for (int c = 0; c < 9; c++) s_feat[tid][c] = f[c];
        s_feat[tid][9]  = xx;
        s_feat[tid][10] = 0.f;
        s_feat[tid][11] = 0.f;
    }
    __syncthreads();

    // ---- phase 3: top-8 by packed(2*<xt,xj> - xx_j, j) ----
    unsigned* cand = reinterpret_cast<unsigned*>(s_a);  // [200][8]
    const int h = nv >> 1;
    const int items = 2 * nv;
    for (int item = tid; item < items; item += 128) {
        int t    = item >> 1;
        int half = item & 1;
        int j0 = half ? h  : 0;
        int j1 = half ? nv : h;
        const float4* fr = reinterpret_cast<const float4*>(s_feat[t]);
        float4 fa = fr[0], fb = fr[1];
        float  f8 = s_feat[t][8];

        unsigned v[KNN];
#pragma unroll
        for (int k = 0; k < KNN; k++) v[k] = 0u;

#pragma unroll 2
        for (int j = j0; j < j1; j++) {
            const float* row = s_feat[j];
            float4 ja = reinterpret_cast<const float4*>(row)[0];
            float4 jb = reinterpret_cast<const float4*>(row)[1];
            float2 jc = *reinterpret_cast<const float2*>(row + 8);
            float i0 = 0.f, i1 = -0.5f * jc.y;   // fold -xx_j/2 into chain 1
            i0 = fmaf(fa.x, ja.x, i0);  i1 = fmaf(fa.y, ja.y, i1);
            i0 = fmaf(fa.z, ja.z, i0);  i1 = fmaf(fa.w, ja.w, i1);
            i0 = fmaf(fb.x, jb.x, i0);  i1 = fmaf(fb.y, jb.y, i1);
            i0 = fmaf(fb.z, jb.z, i0);  i1 = fmaf(fb.w, jb.w, i1);
            i0 = fmaf(f8,   jc.x, i0);
            float key = 2.0f * (i0 + i1);        // = 2*inner - xx_j
            ins8p(v, packkey(key, j));
        }
#pragma unroll
        for (int k = 0; k < KNN; k++) cand[item * KNN + k] = v[k];
    }
    __syncthreads();

    // merge halves per point (packed => stability automatic), fill masked (key==0)
    if (tid < nv) {
        const int t = tid;
        unsigned v[KNN];
#pragma unroll
        for (int k = 0; k < KNN; k++) v[k] = cand[(2 * t) * KNN + k];
#pragma unroll
        for (int k = 0; k < KNN; k++) ins8p(v, cand[(2 * t + 1) * KNN + k]);
        // masked points: key exactly 0.0, ascending index
        const unsigned mbase = ((ordf(0.0f) + 0x40u) & 0xFFFFFF80u);
        for (int jm = nv; jm < TPTS; jm++) {
            unsigned p = mbase | (unsigned)(127 - jm);
            if (!(p > v[KNN - 1])) break;
            ins8p(v, p);
        }
#pragma unroll
        for (int k = 0; k < KNN; k++)
            s_idx[t][k] = (unsigned char)(127u - (v[k] & 0x7Fu));
    }
    __syncthreads();

    // ---- phase 2: a'[t][o] = feat[t] . wa[:,o] (overwrites candidate overlay) ----
    for (int p = tid; p < TPTS * 16; p += 128) {
        int t  = p >> 4;
        int o4 = p & 15;
        const float4* fr = reinterpret_cast<const float4*>(s_feat[t]);
        float4 fa = fr[0], fb = fr[1];
        float  f8 = s_feat[t][8];
        float fs[9] = {fa.x, fa.y, fa.z, fa.w, fb.x, fb.y, fb.z, fb.w, f8};
        float4 acc = make_float4(0.f, 0.f, 0.f, 0.f);
#pragma unroll
        for (int c = 0; c < 9; c++) {
            float4 wv = *reinterpret_cast<const float4*>(&s_wa[c * 64 + o4 * 4]);
            acc.x = fmaf(fs[c], wv.x, acc.x);
            acc.y = fmaf(fs[c], wv.y, acc.y);
            acc.z = fmaf(fs[c], wv.z, acc.z);
            acc.w = fmaf(fs[c], wv.w, acc.w);
        }
        reinterpret_cast<float4*>(s_a)[t * 16 + o4] = acc;
    }
    __syncthreads();

    // ---- phase 4 (o4 = low bits => contiguous gathers; scr overlays dead s_wa) ----
    float* s_scr = s_wa;   // 512 floats needed, s_wa has 576
    {
        const int o4    = tid & 15;
        const int slice = tid >> 4;   // 0..7
        float4 rmax = make_float4(0.f, 0.f, 0.f, 0.f);
        for (int t = slice; t < nv; t += 8) {
            float4 m4 = make_float4(-3.402823466e38f, -3.402823466e38f,
                                    -3.402823466e38f, -3.402823466e38f);
#pragma unroll
            for (int k = 0; k < KNN; k++) {
                int j = (int)s_idx[t][k];
                float4 a = reinterpret_cast<const float4*>(s_a)[j * 16 + o4];
                m4.x = fmaxf(m4.x, a.x);
                m4.y = fmaxf(m4.y, a.y);
                m4.z = fmaxf(m4.z, a.z);
                m4.w = fmaxf(m4.w, a.w);
            }
            const float4* fr = reinterpret_cast<const float4*>(s_feat[t]);
            float4 fa = fr[0], fb = fr[1];
            float  f8 = s_feat[t][8];
            float fs[9] = {fa.x, fa.y, fa.z, fa.w, fb.x, fb.y, fb.z, fb.w, f8};
            float4 b = *reinterpret_cast<const float4*>(&s_bias[o4 * 4]);
#pragma unroll
            for (int c = 0; c < 9; c++) {
                float4 wv = *reinterpret_cast<const float4*>(&s_wb[c * 64 + o4 * 4]);
                b.x = fmaf(fs[c], wv.x, b.x);
                b.y = fmaf(fs[c], wv.y, b.y);
                b.z = fmaf(fs[c], wv.z, b.z);
                b.w = fmaf(fs[c], wv.w, b.w);
            }
            float4 hh;
            hh.x = m4.x + b.x;  hh.y = m4.y + b.y;
            hh.z = m4.z + b.z;  hh.w = m4.w + b.w;
            hh.x = (hh.x >= 0.f) ? hh.x : 0.2f * hh.x;
            hh.y = (hh.y >= 0.f) ? hh.y : 0.2f * hh.y;
            hh.z = (hh.z >= 0.f) ? hh.z : 0.2f * hh.z;
            hh.w = (hh.w >= 0.f) ? hh.w : 0.2f * hh.w;
            rmax.x = fmaxf(rmax.x, hh.x);
            rmax.y = fmaxf(rmax.y, hh.y);
            rmax.z = fmaxf(rmax.z, hh.z);
            rmax.w = fmaxf(rmax.w, hh.w);
        }
        reinterpret_cast<float4*>(s_scr)[slice * 16 + o4] = rmax;
    }
    __syncthreads();

    if (tid < 64) {
        float r = s_scr[tid];
#pragma unroll
        for (int s = 1; s < 8; s++) r = fmaxf(r, s_scr[s * 64 + tid]);
        out[vox * 64 + tid] = r;
    }
}

extern "C" void kernel_launch(void* const* d_in, const int* in_sizes, int n_in,
                              void* d_out, int out_size) {
    const float* features   = (const float*)d_in[0];
    const float* conv_w     = (const float*)d_in[1];
    const float* bn_gamma   = (const float*)d_in[2];
    const float* bn_beta    = (const float*)d_in[3];
    const float* bn_mean    = (const float*)d_in[4];
    const float* bn_var     = (const float*)d_in[5];
    const int*   num_voxels = (const int*)d_in[6];
    const int*   coors      = (const int*)d_in[7];
    float*       out        = (float*)d_out;

    gcn_kernel<<<VOX, 128>>>(features, conv_w, bn_gamma, bn_beta, bn_mean, bn_var,
                             num_voxels, coors, out);
}

// round 6
// speedup vs baseline: 2.1356x; 1.0010x over previous
#include <cuda_runtime.h>
#include <math.h>

#define VOX   4096
#define TPTS  100
#define KNN   8

// order-preserving float -> u32 (monotone increasing)
__device__ __forceinline__ unsigned ordf(float f) {
    unsigned u = __float_as_uint(f);
    unsigned m = (unsigned)((int)u >> 31);          // all-ones if negative
    return u ^ (m | 0x80000000u);
}
// pack: top 25 key bits (rounded) | (127 - j)  => desc sort = larger key, then lower j
__device__ __forceinline__ unsigned packkey(float key, int j) {
    unsigned u = ordf(key);
    return ((u + 0x40u) & 0xFFFFFF80u) | (unsigned)(127 - j);
}

// branchless top-8 insert on packed u32: 2 IMNMX per stage
__device__ __forceinline__ void ins8p(unsigned v[KNN], unsigned d) {
#pragma unroll
    for (int s = 0; s < KNN; s++) {
        unsigned vs = v[s];
        v[s] = vs > d ? vs : d;   // umax
        d    = vs > d ? d : vs;   // umin
    }
}

// packed f32x2 helpers (Blackwell)
__device__ __forceinline__ unsigned long long fma_f32x2(
    unsigned long long a, unsigned long long b, unsigned long long c) {
    unsigned long long d;
    asm("fma.rn.f32x2 %0, %1, %2, %3;" : "=l"(d) : "l"(a), "l"(b), "l"(c));
    return d;
}
__device__ __forceinline__ unsigned long long pack2(float lo, float hi) {
    unsigned long long r;
    asm("mov.b64 %0, {%1, %2};" : "=l"(r) : "f"(lo), "f"(hi));
    return r;
}
__device__ __forceinline__ void unpack2(float& lo, float& hi, unsigned long long v) {
    asm("mov.b64 {%0, %1}, %2;" : "=f"(lo), "=f"(hi) : "l"(v));
}

__global__ __launch_bounds__(128, 6) void gcn_kernel(
    const float* __restrict__ features,   // [4096,100,4]
    const float* __restrict__ conv_w,     // [64,18]
    const float* __restrict__ bn_gamma,
    const float* __restrict__ bn_beta,
    const float* __restrict__ bn_mean,
    const float* __restrict__ bn_var,
    const int*   __restrict__ num_voxels, // [4096]
    const int*   __restrict__ coors,      // [4096,4]
    float*       __restrict__ out)        // [4096,64]
{
    __shared__ __align__(16) float s_feat[TPTS][12];  // 9 feat, [9]=xx
    __shared__ __align__(16) float s_a[TPTS * 64];    // a'; overlaid w/ topk candidates
    __shared__ __align__(16) float s_wa[9 * 64];      // dead after phase 2 -> scr overlay
    __shared__ __align__(16) float s_wb[9 * 64];
    __shared__ __align__(16) float s_bias[64];
    __shared__ unsigned char s_idx[TPTS][KNN];
    __shared__ float s_red[16];
    __shared__ float s_mean[3];

    const int tid = threadIdx.x;
    const int vox = blockIdx.x;
    int nv = num_voxels[vox];
    if (nv < 1) nv = 1;
    if (nv > TPTS) nv = TPTS;

    // ---- fold BN into weights (overlaps feature load) ----
    if (tid < 64) {
        const int o = tid;
        float scale = bn_gamma[o] * rsqrtf(bn_var[o] + 1e-3f);
#pragma unroll
        for (int c = 0; c < 9; c++) {
            float w1 = conv_w[o * 18 + c];
            float w2 = conv_w[o * 18 + 9 + c];
            s_wa[c * 64 + o] = w1 * scale;
            s_wb[c * 64 + o] = (w2 - w1) * scale;
        }
        s_bias[o] = bn_beta[o] - bn_mean[o] * scale;
    }

    // ---- phase 1: load + mean over first 3 channels ----
    float4 fv = make_float4(0.f, 0.f, 0.f, 0.f);
    if (tid < TPTS)
        fv = reinterpret_cast<const float4*>(features)[vox * TPTS + tid];
    float sx = (tid < TPTS) ? fv.x : 0.f;
    float sy = (tid < TPTS) ? fv.y : 0.f;
    float sz = (tid < TPTS) ? fv.z : 0.f;
#pragma unroll
    for (int o = 16; o > 0; o >>= 1) {
        sx += __shfl_down_sync(0xffffffffu, sx, o);
        sy += __shfl_down_sync(0xffffffffu, sy, o);
        sz += __shfl_down_sync(0xffffffffu, sz, o);
    }
    if ((tid & 31) == 0) {
        int w = tid >> 5;
        s_red[w] = sx; s_red[4 + w] = sy; s_red[8 + w] = sz;
    }
    __syncthreads();
    if (tid == 0) {
        float fnv = (float)nv;
        s_mean[0] = (s_red[0] + s_red[1] + s_red[2] + s_red[3]) / fnv;
        s_mean[1] = (s_red[4] + s_red[5] + s_red[6] + s_red[7]) / fnv;
        s_mean[2] = (s_red[8] + s_red[9] + s_red[10] + s_red[11]) / fnv;
    }
    __syncthreads();

    const float cx = (float)coors[vox * 4 + 3] * 0.2f + 0.1f;
    const float cy = (float)coors[vox * 4 + 2] * 0.2f + (-39.9f);
    if (tid < TPTS) {
        float m = (tid < nv) ? 1.0f : 0.0f;
        float f[9];
        f[0] = fv.x * m;  f[1] = fv.y * m;  f[2] = fv.z * m;  f[3] = fv.w * m;
        f[4] = (fv.x - s_mean[0]) * m;
        f[5] = (fv.y - s_mean[1]) * m;
        f[6] = (fv.z - s_mean[2]) * m;
        f[7] = (fv.x - cx) * m;
        f[8] = (fv.y - cy) * m;
        float xx = 0.f;
#pragma unroll
        for (int c = 0; c < 9; c++) xx = fmaf(f[c], f[c], xx);
#pragma unroll
        for (int c = 0; c < 9; c++) s_feat[tid][c] = f[c];
        s_feat[tid][9]  = xx;
        s_feat[tid][10] = 0.f;
        s_feat[tid][11] = 0.f;
    }
    __syncthreads();

    // ---- phase 3: top-8 by key = <xt,xj> - xx_j/2 - xx_t/2 (= negdist/2, near 0
    //      at the decision boundary => fine quantization). Quarter-major items so
    //      warp lanes scan the SAME j (broadcast LDS). ----
    unsigned* cand = reinterpret_cast<unsigned*>(s_a);  // [4*TPTS][8]
    const int nv2 = 2 * nv, nv3 = 3 * nv;
    const int items = 4 * nv;
    for (int it = tid; it < items; it += 128) {
        int q = (it >= nv) + (it >= nv2) + (it >= nv3);
        int t = it - q * nv;
        int j0 = (q * nv) >> 2;
        int j1 = ((q + 1) * nv) >> 2;

        const float4* fr = reinterpret_cast<const float4*>(s_feat[t]);
        float4 fa = fr[0], fb = fr[1];
        const float f8  = s_feat[t][8];
        const float xxh = -0.5f * s_feat[t][9];
        const unsigned long long fa01 = pack2(fa.x, fa.y);
        const unsigned long long fa23 = pack2(fa.z, fa.w);
        const unsigned long long fb01 = pack2(fb.x, fb.y);
        const unsigned long long fb23 = pack2(fb.z, fb.w);

        unsigned v[KNN];
#pragma unroll
        for (int k = 0; k < KNN; k++) v[k] = 0u;

#pragma unroll 2
        for (int j = j0; j < j1; j++) {
            const float* row = s_feat[j];
            const ulonglong2 jv = *reinterpret_cast<const ulonglong2*>(row);     // ja01, ja23
            const ulonglong2 jw = *reinterpret_cast<const ulonglong2*>(row + 4); // jb01, jb23
            const float2 jc = *reinterpret_cast<const float2*>(row + 8);
            unsigned long long acc = fma_f32x2(fa01, jv.x, 0ull);
            acc = fma_f32x2(fa23, jv.y, acc);
            acc = fma_f32x2(fb01, jw.x, acc);
            acc = fma_f32x2(fb23, jw.y, acc);
            float lo, hi; unpack2(lo, hi, acc);
            float s = fmaf(-0.5f, jc.y, xxh);
            s = fmaf(f8, jc.x, s);
            float key = (lo + hi) + s;
            ins8p(v, packkey(key, j));
        }
#pragma unroll
        for (int k = 0; k < KNN; k++) cand[it * KNN + k] = v[k];
    }
    __syncthreads();

    // merge 4 quarter-lists per point (packed keys unique => any order), fill masked
    if (tid < nv) {
        const int t = tid;
        unsigned v[KNN];
#pragma unroll
        for (int k = 0; k < KNN; k++) v[k] = cand[t * KNN + k];
#pragma unroll
        for (int k = 0; k < KNN; k++) ins8p(v, cand[(nv + t) * KNN + k]);
#pragma unroll
        for (int k = 0; k < KNN; k++) ins8p(v, cand[(nv2 + t) * KNN + k]);
#pragma unroll
        for (int k = 0; k < KNN; k++) ins8p(v, cand[(nv3 + t) * KNN + k]);
        // masked points j>=nv: key exactly -xx_t/2 (matches scan path bit-for-bit)
        const float mkey = -0.5f * s_feat[t][9];
        const unsigned mbase = (ordf(mkey) + 0x40u) & 0xFFFFFF80u;
        for (int jm = nv; jm < TPTS; jm++) {
            unsigned p = mbase | (unsigned)(127 - jm);
            if (!(p > v[KNN - 1])) break;
            ins8p(v, p);
        }
#pragma unroll
        for (int k = 0; k < KNN; k++)
            s_idx[t][k] = (unsigned char)(127u - (v[k] & 0x7Fu));
    }
    __syncthreads();

    // ---- phase 2: a'[t][o] = feat[t] . wa[:,o] (overwrites candidate overlay) ----
    for (int p = tid; p < TPTS * 16; p += 128) {
        int t  = p >> 4;
        int o4 = p & 15;
        const float4* fr = reinterpret_cast<const float4*>(s_feat[t]);
        float4 fa = fr[0], fb = fr[1];
        float  f8 = s_feat[t][8];
        float fs[9] = {fa.x, fa.y, fa.z, fa.w, fb.x, fb.y, fb.z, fb.w, f8};
        float4 acc = make_float4(0.f, 0.f, 0.f, 0.f);
#pragma unroll
        for (int c = 0; c < 9; c++) {
            float4 wv = *reinterpret_cast<const float4*>(&s_wa[c * 64 + o4 * 4]);
            acc.x = fmaf(fs[c], wv.x, acc.x);
            acc.y = fmaf(fs[c], wv.y, acc.y);
            acc.z = fmaf(fs[c], wv.z, acc.z);
            acc.w = fmaf(fs[c], wv.w, acc.w);
        }
        reinterpret_cast<float4*>(s_a)[t * 16 + o4] = acc;
    }
    __syncthreads();

    // ---- phase 4 (o4 = low bits => contiguous gathers; scr overlays dead s_wa) ----
    float* s_scr = s_wa;   // 512 floats needed, s_wa has 576
    {
        const int o4    = tid & 15;
        const int slice = tid >> 4;   // 0..7
        float4 rmax = make_float4(0.f, 0.f, 0.f, 0.f);
        for (int t = slice; t < nv; t += 8) {
            float4 m4 = make_float4(-3.402823466e38f, -3.402823466e38f,
                                    -3.402823466e38f, -3.402823466e38f);
#pragma unroll
            for (int k = 0; k < KNN; k++) {
                int j = (int)s_idx[t][k];
                float4 a = reinterpret_cast<const float4*>(s_a)[j * 16 + o4];
                m4.x = fmaxf(m4.x, a.x);
                m4.y = fmaxf(m4.y, a.y);
                m4.z = fmaxf(m4.z, a.z);
                m4.w = fmaxf(m4.w, a.w);
            }
            const float4* fr = reinterpret_cast<const float4*>(s_feat[t]);
            float4 fa = fr[0], fb = fr[1];
            float  f8 = s_feat[t][8];
            float fs[9] = {fa.x, fa.y, fa.z, fa.w, fb.x, fb.y, fb.z, fb.w, f8};
            float4 b = *reinterpret_cast<const float4*>(&s_bias[o4 * 4]);
#pragma unroll
            for (int c = 0; c < 9; c++) {
                float4 wv = *reinterpret_cast<const float4*>(&s_wb[c * 64 + o4 * 4]);
                b.x = fmaf(fs[c], wv.x, b.x);
                b.y = fmaf(fs[c], wv.y, b.y);
                b.z = fmaf(fs[c], wv.z, b.z);
                b.w = fmaf(fs[c], wv.w, b.w);
            }
            float4 hh;
            hh.x = m4.x + b.x;  hh.y = m4.y + b.y;
            hh.z = m4.z + b.z;  hh.w = m4.w + b.w;
            hh.x = (hh.x >= 0.f) ? hh.x : 0.2f * hh.x;
            hh.y = (hh.y >= 0.f) ? hh.y : 0.2f * hh.y;
            hh.z = (hh.z >= 0.f) ? hh.z : 0.2f * hh.z;
            hh.w = (hh.w >= 0.f) ? hh.w : 0.2f * hh.w;
            rmax.x = fmaxf(rmax.x, hh.x);
            rmax.y = fmaxf(rmax.y, hh.y);
            rmax.z = fmaxf(rmax.z, hh.z);
            rmax.w = fmaxf(rmax.w, hh.w);
        }
        reinterpret_cast<float4*>(s_scr)[slice * 16 + o4] = rmax;
    }
    __syncthreads();

    if (tid < 64) {
        float r = s_scr[tid];
#pragma unroll
        for (int s = 1; s < 8; s++) r = fmaxf(r, s_scr[s * 64 + tid]);
        out[vox * 64 + tid] = r;
    }
}

extern "C" void kernel_launch(void* const* d_in, const int* in_sizes, int n_in,
                              void* d_out, int out_size) {
    const float* features   = (const float*)d_in[0];
    const float* conv_w     = (const float*)d_in[1];
    const float* bn_gamma   = (const float*)d_in[2];
    const float* bn_beta    = (const float*)d_in[3];
    const float* bn_mean    = (const float*)d_in[4];
    const float* bn_var     = (const float*)d_in[5];
    const int*   num_voxels = (const int*)d_in[6];
    const int*   coors      = (const int*)d_in[7];
    float*       out        = (float*)d_out;

    gcn_kernel<<<VOX, 128>>>(features, conv_w, bn_gamma, bn_beta, bn_mean, bn_var,
                             num_voxels, coors, out);
}